// round 7
// baseline (speedup 1.0000x reference)
#include <cuda_runtime.h>
#include <cuda_fp16.h>
#include <cstdint>
#include <math.h>

// ITAttention on GB300, sm_103 baseline ISA. mma.sync.m16n8k16 fp16 HMMA.
// Pipeline (associativity-restructured): o = A_sm @ (L^T @ ov)
// R7: B-fragment software pipelining (double-buffered ldmatrix), merged
// G1/G3/G5 projection launch, TT GEMM for the L^T@ov contraction.

#define D_MODEL 1024
#define T_SEQ   2048
#define NB      4
#define MTOT    (NB * T_SEQ)       // 8192

// ---------------- scratch (no allocation allowed) ----------------
__device__ __align__(256) __half g_lat_h[MTOT * D_MODEL];
__device__ __align__(256) __half g_in_h [MTOT * D_MODEL];
__device__ __align__(256) __half g_w_h  [5 * D_MODEL * D_MODEL];
__device__ __align__(256) __half g_p1_h [MTOT * D_MODEL];          // emb0
__device__ __align__(256) __half g_p2_h [MTOT * D_MODEL];          // Dm
__device__ __align__(256) __half g_ls_h [MTOT * D_MODEL];          // L (row-softmaxed) [q,j]
__device__ __align__(256) __half g_ov_h [MTOT * D_MODEL];          // ov [q,e]
__device__ __align__(256) __half g_mm_h [NB * D_MODEL * D_MODEL];  // MmT [e,j]
__device__ __align__(256) __half g_pa_h [MTOT * D_MODEL];          // col-softmaxed A
__device__ __align__(256) float  g_f1  [MTOT * D_MODEL];           // fp32 staging (s1)
__device__ __align__(256) float  g_f2  [MTOT * D_MODEL];           // fp32 staging (S2)

// ---------------- helpers ----------------
__device__ __forceinline__ uint32_t smem_u32(const void* p) {
    uint32_t a;
    asm("{ .reg .u64 t; cvta.to.shared.u64 t, %1; cvt.u32.u64 %0, t; }" : "=r"(a) : "l"(p));
    return a;
}
__device__ __forceinline__ void cp16(uint32_t dst, const void* src) {
    asm volatile("cp.async.cg.shared.global [%0], [%1], 16;" :: "r"(dst), "l"(src) : "memory");
}
__device__ __forceinline__ void cp_commit() {
    asm volatile("cp.async.commit_group;" ::: "memory");
}

#define LDSM4(r, addr)                                                            \
    asm volatile("ldmatrix.sync.aligned.m8n8.x4.shared.b16 {%0,%1,%2,%3}, [%4];"  \
                 : "=r"((r)[0]), "=r"((r)[1]), "=r"((r)[2]), "=r"((r)[3])         \
                 : "r"(addr))

#define LDSM4T(r, addr)                                                                 \
    asm volatile("ldmatrix.sync.aligned.m8n8.x4.trans.shared.b16 {%0,%1,%2,%3}, [%4];"  \
                 : "=r"((r)[0]), "=r"((r)[1]), "=r"((r)[2]), "=r"((r)[3])               \
                 : "r"(addr))

#define MMA_F16(d, a, b)                                                           \
    asm volatile("mma.sync.aligned.m16n8k16.row.col.f32.f16.f16.f32 "              \
                 "{%0,%1,%2,%3}, {%4,%5,%6,%7}, {%8,%9}, {%0,%1,%2,%3};"           \
                 : "+f"((d)[0]), "+f"((d)[1]), "+f"((d)[2]), "+f"((d)[3])          \
                 : "r"((a)[0]), "r"((a)[1]), "r"((a)[2]), "r"((a)[3]),             \
                   "r"((b)[0]), "r"((b)[1]))

// ---------------- common GEMM config ----------------
// BM=128, BN=256, BK=64. 256 threads = 8 warps (2x4), warp tile 64x64.
// smem/stage: A 16K | B 32K = 48KB; 4 stages = 192KB.
#define STG_BYTES 49152u
#define NSTAGE    4
#define SMEM_BYTES (NSTAGE * 49152)

// =======================================================================
// gemm_body: C[M,N] tile = A[M,K] @ B[N,K]^T (+bias), both K-contiguous.
// Ah/Bh pre-offset to the (bm, bn) tile. B-fragment software pipelining.
// =======================================================================
#define LOAD_STAGE(sidx) do {                                                        \
    const uint32_t base_ = sb + (uint32_t)((sidx) & 3) * STG_BYTES;                  \
    const int k0_ = (sidx) * 64;                                                     \
    _Pragma("unroll")                                                                \
    for (int t_ = 0; t_ < 4; t_++) {                                                 \
        int idx_ = tid + 256 * t_;                                                   \
        int r_ = idx_ >> 3, c_ = idx_ & 7;                                           \
        uint32_t sm_ = base_ + (uint32_t)r_ * 128u +                                 \
                       ((uint32_t)(c_ * 16) ^ ((uint32_t)(r_ & 7) * 16u));           \
        cp16(sm_, Ah + (size_t)r_ * K + k0_ + c_ * 8);                               \
    }                                                                                \
    _Pragma("unroll")                                                                \
    for (int t_ = 0; t_ < 8; t_++) {                                                 \
        int idx_ = tid + 256 * t_;                                                   \
        int r_ = idx_ >> 3, c_ = idx_ & 7;                                           \
        uint32_t sm_ = base_ + 16384u + (uint32_t)r_ * 128u +                        \
                       ((uint32_t)(c_ * 16) ^ ((uint32_t)(r_ & 7) * 16u));           \
        cp16(sm_, Bh + (size_t)r_ * K + k0_ + c_ * 8);                               \
    }                                                                                \
    cp_commit();                                                                     \
} while (0)

__device__ __forceinline__ void gemm_body(
    const __half* __restrict__ Ah, const __half* __restrict__ Bh,
    const float* __restrict__ bias,
    float* __restrict__ Cf, __half* __restrict__ Ch,
    int N, int K, int bm, int bn, long long cOff)
{
    extern __shared__ char smem[];
    const uint32_t sb = smem_u32(smem);
    const int tid = threadIdx.x, lane = tid & 31, wid = tid >> 5;
    const int wm = wid >> 2, wn = wid & 3;

    const int nst = K >> 6;

    LOAD_STAGE(0);
    LOAD_STAGE(1);
    LOAD_STAGE(2);

    const uint32_t swz = ((uint32_t)(lane & 7)) << 4;
    const uint32_t acsel = (uint32_t)(lane >> 4);
    uint32_t aoff[4];
#pragma unroll
    for (int i = 0; i < 4; i++)
        aoff[i] = (uint32_t)(wm * 64 + i * 16 + (lane & 15)) * 128u;
    const uint32_t bcsel = (uint32_t)((lane >> 3) & 1);
    const int brow = (lane & 7) + ((lane >> 4) << 3);
    uint32_t boff[4];
#pragma unroll
    for (int jj = 0; jj < 4; jj++)
        boff[jj] = 16384u + (uint32_t)(wn * 64 + jj * 16 + brow) * 128u;

    float acc[4][8][4];
#pragma unroll
    for (int i = 0; i < 4; i++)
#pragma unroll
        for (int j = 0; j < 8; j++)
#pragma unroll
            for (int r = 0; r < 4; r++) acc[i][j][r] = 0.f;

    for (int s = 0; s < nst; s++) {
        const int rem = nst - 1 - s;
        if (rem >= 2)      asm volatile("cp.async.wait_group 2;" ::: "memory");
        else if (rem == 1) asm volatile("cp.async.wait_group 1;" ::: "memory");
        else               asm volatile("cp.async.wait_group 0;" ::: "memory");
        __syncthreads();
        if (s + 3 < nst) LOAD_STAGE(s + 3);

        const uint32_t st = sb + (uint32_t)(s & 3) * STG_BYTES;

        // B-fragment double buffer: prefetch next ldmatrix before the MMAs
        uint32_t bfr[2][4];
        LDSM4(bfr[0], st + boff[0] + ((bcsel << 4) ^ swz));
        int pb = 0;
#pragma unroll
        for (int ks = 0; ks < 4; ks++) {
            uint32_t af[4][4];
            const uint32_t ak = (((uint32_t)(2 * ks) + acsel) << 4) ^ swz;
#pragma unroll
            for (int i = 0; i < 4; i++)
                LDSM4(af[i], st + aoff[i] + ak);
#pragma unroll
            for (int jj = 0; jj < 4; jj++) {
                if (!(jj == 3 && ks == 3)) {
                    const int njj = (jj + 1) & 3;
                    const int nks = (jj == 3) ? ks + 1 : ks;
                    const uint32_t nbk = (((uint32_t)(2 * nks) + bcsel) << 4) ^ swz;
                    LDSM4(bfr[pb ^ 1], st + boff[njj] + nbk);
                }
#pragma unroll
                for (int i = 0; i < 4; i++) {
                    MMA_F16(acc[i][jj * 2 + 0], af[i], bfr[pb]);
                    MMA_F16(acc[i][jj * 2 + 1], af[i], bfr[pb] + 2);
                }
                pb ^= 1;
            }
        }
    }

    const int g = lane >> 2, tig = lane & 3;
    float bv[8][2];
#pragma unroll
    for (int j = 0; j < 8; j++) {
        const int n = bn + wn * 64 + j * 8 + tig * 2;
        bv[j][0] = bias ? bias[n] : 0.f;
        bv[j][1] = bias ? bias[n + 1] : 0.f;
    }
#pragma unroll
    for (int i = 0; i < 4; i++) {
        const long long m0 = bm + wm * 64 + i * 16 + g;
#pragma unroll
        for (int j = 0; j < 8; j++) {
            const int n = bn + wn * 64 + j * 8 + tig * 2;
#pragma unroll
            for (int h = 0; h < 2; h++) {
                const float v0 = acc[i][j][2 * h]     + bv[j][0];
                const float v1 = acc[i][j][2 * h + 1] + bv[j][1];
                const long long o = cOff + (m0 + 8 * h) * (long long)N + n;
                if (Cf) *(float2*)(Cf + o) = make_float2(v0, v1);
                else    *(__half2*)(Ch + o) = __floats2half2_rn(v0, v1);
            }
        }
    }
}

// generic single-GEMM wrapper (G2, G4, G7)
__global__ void __launch_bounds__(256, 1)
gemm_f16(const __half* __restrict__ Ah, const __half* __restrict__ Bh,
         const float* __restrict__ bias,
         float* __restrict__ Cf, __half* __restrict__ Ch,
         int N, int K,
         long long aB, long long bB, long long cB)
{
    const long long z = blockIdx.z;
    const int bm = blockIdx.y * 128, bn = blockIdx.x * 256;
    gemm_body(Ah + z * aB + (long long)bm * K,
              Bh + z * bB + (long long)bn * K,
              bias, Cf, Ch, N, K, bm, bn, z * cB);
}

// merged G1/G3/G5: grid.z in {0,1,2} selects the job. All M=8192,N=K=1024,
// fp16 out, bias present.
__global__ void __launch_bounds__(256, 1)
gemm_f16_proj3(const __half* __restrict__ A0, const __half* __restrict__ A1,
               const __half* __restrict__ A2, const __half* __restrict__ W,
               const float* __restrict__ b0, const float* __restrict__ b1,
               const float* __restrict__ b2,
               __half* __restrict__ C0, __half* __restrict__ C1,
               __half* __restrict__ C2)
{
    const int zz = blockIdx.z;
    const int NW = D_MODEL * D_MODEL;
    const __half* A = (zz == 0) ? A0 : (zz == 1) ? A1 : A2;
    const __half* B = (zz == 0) ? W : (zz == 1) ? W + 2 * NW : W + 4 * NW;
    const float* bias = (zz == 0) ? b0 : (zz == 1) ? b1 : b2;
    __half* C = (zz == 0) ? C0 : (zz == 1) ? C1 : C2;
    const int bm = blockIdx.y * 128, bn = blockIdx.x * 256;
    gemm_body(A + (long long)bm * D_MODEL, B + (long long)bn * D_MODEL,
              bias, nullptr, C, D_MODEL, D_MODEL, bm, bn, 0);
}

// =======================================================================
// gemm_f16_tt: C[e,j] = sum_q A[q,e] * B[q,j]  (both stored [K=q, 1024])
// ldmatrix.trans both operands; B-fragment double buffering.
// =======================================================================
#define LOAD_STAGE_TT(sidx) do {                                                     \
    const uint32_t base_ = sb + (uint32_t)((sidx) & 3) * STG_BYTES;                  \
    const int k0_ = (sidx) * 64;                                                     \
    _Pragma("unroll")                                                                \
    for (int t_ = 0; t_ < 4; t_++) {                                                 \
        int idx_ = tid + 256 * t_;                                                   \
        int r_ = idx_ >> 4, u_ = idx_ & 15;                                          \
        uint32_t sm_ = base_ + (uint32_t)r_ * 256u +                                 \
                       ((uint32_t)(u_ ^ (r_ & 7)) << 4);                             \
        cp16(sm_, Ag + (size_t)(k0_ + r_) * D_MODEL + bm + u_ * 8);                  \
    }                                                                                \
    _Pragma("unroll")                                                                \
    for (int t_ = 0; t_ < 8; t_++) {                                                 \
        int idx_ = tid + 256 * t_;                                                   \
        int r_ = idx_ >> 5, u_ = idx_ & 31;                                          \
        uint32_t sm_ = base_ + 16384u + (uint32_t)r_ * 512u +                        \
                       ((uint32_t)(u_ ^ (r_ & 7)) << 4);                             \
        cp16(sm_, Bg + (size_t)(k0_ + r_) * D_MODEL + bn + u_ * 8);                  \
    }                                                                                \
    cp_commit();                                                                     \
} while (0)

__global__ void __launch_bounds__(256, 1)
gemm_f16_tt(const __half* __restrict__ A, const __half* __restrict__ B,
            __half* __restrict__ C, int Kdim,
            long long aB, long long bB, long long cB)
{
    extern __shared__ char smem[];
    const uint32_t sb = smem_u32(smem);
    const int tid = threadIdx.x, lane = tid & 31, wid = tid >> 5;
    const int wm = wid >> 2, wn = wid & 3;
    const long long z = blockIdx.z;
    const int bm = blockIdx.y * 128, bn = blockIdx.x * 256;

    const __half* Ag = A + z * aB;
    const __half* Bg = B + z * bB;

    const int nst = Kdim >> 6;

    LOAD_STAGE_TT(0);
    LOAD_STAGE_TT(1);
    LOAD_STAGE_TT(2);

    const uint32_t l7 = (uint32_t)(lane & 7);
    const int arow_k = ((lane >> 4) << 3) + (lane & 7);
    const uint32_t auadd = (uint32_t)((lane >> 3) & 1);
    const int brow_k = (((lane >> 3) & 1) << 3) + (lane & 7);
    const uint32_t buadd = (uint32_t)(lane >> 4);

    float acc[4][8][4];
#pragma unroll
    for (int i = 0; i < 4; i++)
#pragma unroll
        for (int j = 0; j < 8; j++)
#pragma unroll
            for (int r = 0; r < 4; r++) acc[i][j][r] = 0.f;

    for (int s = 0; s < nst; s++) {
        const int rem = nst - 1 - s;
        if (rem >= 2)      asm volatile("cp.async.wait_group 2;" ::: "memory");
        else if (rem == 1) asm volatile("cp.async.wait_group 1;" ::: "memory");
        else               asm volatile("cp.async.wait_group 0;" ::: "memory");
        __syncthreads();
        if (s + 3 < nst) LOAD_STAGE_TT(s + 3);

        const uint32_t st = sb + (uint32_t)(s & 3) * STG_BYTES;

        uint32_t bfr[2][4];
        {
            const uint32_t rb0 = (uint32_t)brow_k;
            const uint32_t unit0 = (uint32_t)(wn * 8) + buadd;
            LDSM4T(bfr[0], st + 16384u + rb0 * 512u + ((unit0 ^ l7) << 4));
        }
        int pb = 0;
#pragma unroll
        for (int ks = 0; ks < 4; ks++) {
            const uint32_t ra = (uint32_t)(ks * 16 + arow_k);
            uint32_t af[4][4];
#pragma unroll
            for (int i = 0; i < 4; i++) {
                const uint32_t unit = (uint32_t)(wm * 8 + 2 * i) + auadd;
                LDSM4T(af[i], st + ra * 256u + ((unit ^ l7) << 4));
            }
#pragma unroll
            for (int jj = 0; jj < 4; jj++) {
                if (!(jj == 3 && ks == 3)) {
                    const int njj = (jj + 1) & 3;
                    const int nks = (jj == 3) ? ks + 1 : ks;
                    const uint32_t rbn = (uint32_t)(nks * 16 + brow_k);
                    const uint32_t nunit = (uint32_t)(wn * 8 + 2 * njj) + buadd;
                    LDSM4T(bfr[pb ^ 1], st + 16384u + rbn * 512u + ((nunit ^ l7) << 4));
                }
#pragma unroll
                for (int i = 0; i < 4; i++) {
                    MMA_F16(acc[i][jj * 2 + 0], af[i], bfr[pb]);
                    MMA_F16(acc[i][jj * 2 + 1], af[i], bfr[pb] + 2);
                }
                pb ^= 1;
            }
        }
    }

    const int g = lane >> 2, tig = lane & 3;
#pragma unroll
    for (int i = 0; i < 4; i++) {
        const long long m0 = bm + wm * 64 + i * 16 + g;
#pragma unroll
        for (int j = 0; j < 8; j++) {
            const int n = bn + wn * 64 + j * 8 + tig * 2;
#pragma unroll
            for (int h = 0; h < 2; h++) {
                const long long o = (z * cB) + (m0 + 8 * h) * (long long)D_MODEL + n;
                *(__half2*)(C + o) = __floats2half2_rn(acc[i][j][2 * h],
                                                       acc[i][j][2 * h + 1]);
            }
        }
    }
}

// ---------------- aux kernels ----------------
__global__ __launch_bounds__(256)
void tohalf_kernel(const float4* __restrict__ in, __half2* __restrict__ out, int n4)
{
    int i = blockIdx.x * 256 + threadIdx.x;
    if (i < n4) {
        float4 v = in[i];
        out[2 * i]     = __floats2half2_rn(v.x, v.y);
        out[2 * i + 1] = __floats2half2_rn(v.z, v.w);
    }
}

__global__ __launch_bounds__(256)
void tohalf5_kernel(const float4* __restrict__ w0, const float4* __restrict__ w1,
                    const float4* __restrict__ w2, const float4* __restrict__ w3,
                    const float4* __restrict__ w4, __half2* __restrict__ out)
{
    const int seg = blockIdx.x >> 10;
    const int i = ((blockIdx.x & 1023) * 256 + threadIdx.x);
    const float4* src = (seg == 0) ? w0 : (seg == 1) ? w1 : (seg == 2) ? w2
                       : (seg == 3) ? w3 : w4;
    float4 v = src[i];
    __half2* o = out + (size_t)seg * (D_MODEL * D_MODEL / 2) + 2 * (size_t)i;
    o[0] = __floats2half2_rn(v.x, v.y);
    o[1] = __floats2half2_rn(v.z, v.w);
}

__global__ __launch_bounds__(256)
void softmax_rows_1024(const float* __restrict__ X, __half* __restrict__ O)
{
    const float* p = X + (long long)blockIdx.x * 1024;
    __half* q = O + (long long)blockIdx.x * 1024;
    const int t = threadIdx.x;
    __shared__ float red[256];
    float v[4];
#pragma unroll
    for (int j = 0; j < 4; j++) v[j] = p[t + 256 * j];
    float mx = fmaxf(fmaxf(v[0], v[1]), fmaxf(v[2], v[3]));
    red[t] = mx; __syncthreads();
    for (int s = 128; s > 0; s >>= 1) { if (t < s) red[t] = fmaxf(red[t], red[t + s]); __syncthreads(); }
    mx = red[0]; __syncthreads();
    float s = 0.f;
#pragma unroll
    for (int j = 0; j < 4; j++) { v[j] = __expf(v[j] - mx); s += v[j]; }
    red[t] = s; __syncthreads();
    for (int s2 = 128; s2 > 0; s2 >>= 1) { if (t < s2) red[t] += red[t + s2]; __syncthreads(); }
    const float inv = 1.f / red[0];
#pragma unroll
    for (int j = 0; j < 4; j++) q[t + 256 * j] = __float2half(v[j] * inv);
}

__global__ __launch_bounds__(256)
void softmax_cols_half(const float* __restrict__ X, __half* __restrict__ P)
{
    const int tx = threadIdx.x & 31;
    const int ty = threadIdx.x >> 5;
    const int c = blockIdx.x * 32 + tx;
    const long long zoff = (long long)blockIdx.y * T_SEQ * D_MODEL;
    const float* base = X + zoff + c;

    float mx = -1e30f, s = 0.f;
    for (int r = ty; r < T_SEQ; r += 8) {
        float x = base[(long long)r * D_MODEL];
        if (x > mx) { s = s * __expf(mx - x) + 1.f; mx = x; }
        else        { s += __expf(x - mx); }
    }
    __shared__ float smx[8][32], ssm[8][32];
    smx[ty][tx] = mx; ssm[ty][tx] = s;
    __syncthreads();
    if (ty == 0) {
        float M = smx[0][tx];
#pragma unroll
        for (int k = 1; k < 8; k++) M = fmaxf(M, smx[k][tx]);
        float S = 0.f;
#pragma unroll
        for (int k = 0; k < 8; k++) S += ssm[k][tx] * __expf(smx[k][tx] - M);
        smx[0][tx] = M; ssm[0][tx] = 1.f / S;
    }
    __syncthreads();
    const float M = smx[0][tx], inv = ssm[0][tx];
    for (int r = ty; r < T_SEQ; r += 8) {
        const long long o = zoff + (long long)r * D_MODEL + c;
        P[o] = __float2half(__expf(base[(long long)r * D_MODEL] - M) * inv);
    }
}

// ---------------- host launcher ----------------
extern "C" void kernel_launch(void* const* d_in, const int* in_sizes, int n_in,
                              void* d_out, int out_size)
{
    const float* latent = (const float*)d_in[0];
    const float* input  = (const float*)d_in[1];
    const float* Wl = (const float*)d_in[2];
    const float* bl = (const float*)d_in[3];
    const float* Wu = (const float*)d_in[4];
    const float* bu = (const float*)d_in[5];
    const float* WA = (const float*)d_in[6];
    const float* bA = (const float*)d_in[7];
    const float* WV = (const float*)d_in[8];
    const float* bV = (const float*)d_in[9];
    const float* Wo = (const float*)d_in[10];
    const float* bo = (const float*)d_in[11];
    float* out = (float*)d_out;

    __half *lat_h, *in_h, *w_h, *p1_h, *p2_h, *ls_h, *ov_h, *mm_h, *pa_h;
    float *f1, *f2;
    cudaGetSymbolAddress((void**)&lat_h, g_lat_h);
    cudaGetSymbolAddress((void**)&in_h,  g_in_h);
    cudaGetSymbolAddress((void**)&w_h,   g_w_h);
    cudaGetSymbolAddress((void**)&p1_h,  g_p1_h);
    cudaGetSymbolAddress((void**)&p2_h,  g_p2_h);
    cudaGetSymbolAddress((void**)&ls_h,  g_ls_h);
    cudaGetSymbolAddress((void**)&ov_h,  g_ov_h);
    cudaGetSymbolAddress((void**)&mm_h,  g_mm_h);
    cudaGetSymbolAddress((void**)&pa_h,  g_pa_h);
    cudaGetSymbolAddress((void**)&f1,    g_f1);
    cudaGetSymbolAddress((void**)&f2,    g_f2);

    cudaFuncSetAttribute(gemm_f16,
                         cudaFuncAttributeMaxDynamicSharedMemorySize, SMEM_BYTES);
    cudaFuncSetAttribute(gemm_f16_proj3,
                         cudaFuncAttributeMaxDynamicSharedMemorySize, SMEM_BYTES);
    cudaFuncSetAttribute(gemm_f16_tt,
                         cudaFuncAttributeMaxDynamicSharedMemorySize, SMEM_BYTES);

    const int D = D_MODEL;
    const int NW = D * D;
    const int NACT = MTOT * D;

    // 1-3: operand prep
    tohalf_kernel<<<NACT / 4 / 256, 256>>>((const float4*)latent, (__half2*)lat_h, NACT / 4);
    tohalf_kernel<<<NACT / 4 / 256, 256>>>((const float4*)input,  (__half2*)in_h,  NACT / 4);
    tohalf5_kernel<<<5 * (NW / 4 / 256), 256>>>((const float4*)Wl, (const float4*)Wu,
                                                (const float4*)WA, (const float4*)WV,
                                                (const float4*)Wo, (__half2*)w_h);

    dim3 thr(256);
    dim3 gProj(D / 256, MTOT / 128, 1);       // (4, 64)

    // 4: merged G1/G3/G5 -> p1, p2, ov (fp16), 768 CTAs
    gemm_f16_proj3<<<dim3(D / 256, MTOT / 128, 3), thr, SMEM_BYTES>>>(
        lat_h, in_h, lat_h, w_h, bl, bA, bo, p1_h, p2_h, ov_h);

    // 5: G2: s1 = emb0 @ Wu^T + bu -> f1 (fp32)
    gemm_f16<<<gProj, thr, SMEM_BYTES>>>(p1_h, w_h + 1 * NW, bu,
                                         f1, nullptr, D, D, 0, 0, 0);
    // 6: G4: S2 = Dm @ WV^T + bV -> f2 (fp32)   [ncu profiles this launch]
    gemm_f16<<<gProj, thr, SMEM_BYTES>>>(p2_h, w_h + 3 * NW, bV,
                                         f2, nullptr, D, D, 0, 0, 0);
    // 7: row softmax -> L fp16 [q,j]
    softmax_rows_1024<<<MTOT, 256>>>(f1, ls_h);
    // 8: col softmax over T_kv -> pa fp16
    softmax_cols_half<<<dim3(D / 32, NB), 256>>>(f2, pa_h);

    // 9: G6 (trans-trans): MmT[e,j] = sum_q ov[q,e] * L[q,j]  -> mm fp16
    gemm_f16_tt<<<dim3(D / 256, D / 128, NB), thr, SMEM_BYTES>>>(
        ov_h, ls_h, mm_h, T_SEQ,
        (long long)T_SEQ * D, (long long)T_SEQ * D, (long long)D * D);

    // 10: G7: o[b] = pa @ MmT^T  (M=2048, N=1024, K=1024) -> d_out fp32
    gemm_f16<<<dim3(D / 256, T_SEQ / 128, NB), thr, SMEM_BYTES>>>(
        pa_h, mm_h, nullptr, out, nullptr,
        D, D, (long long)T_SEQ * D, (long long)D * D, (long long)T_SEQ * D);
}

// round 8
// speedup vs baseline: 1.0486x; 1.0486x over previous
#include <cuda_runtime.h>
#include <cuda_fp16.h>
#include <cstdint>
#include <math.h>

// ITAttention on GB300, sm_103 baseline ISA. mma.sync.m16n8k16 fp16 HMMA.
// Pipeline (associativity-restructured): o = A_sm @ (L^T @ ov)
// R8: BM=BN=128 tiles, 3-stage cp.async, 2 CTAs/SM for latency hiding.

#define D_MODEL 1024
#define T_SEQ   2048
#define NB      4
#define MTOT    (NB * T_SEQ)       // 8192

// ---------------- scratch (no allocation allowed) ----------------
__device__ __align__(256) __half g_lat_h[MTOT * D_MODEL];
__device__ __align__(256) __half g_in_h [MTOT * D_MODEL];
__device__ __align__(256) __half g_w_h  [5 * D_MODEL * D_MODEL];
__device__ __align__(256) __half g_p1_h [MTOT * D_MODEL];          // emb0
__device__ __align__(256) __half g_p2_h [MTOT * D_MODEL];          // Dm
__device__ __align__(256) __half g_ls_h [MTOT * D_MODEL];          // L (row-softmaxed) [q,j]
__device__ __align__(256) __half g_ov_h [MTOT * D_MODEL];          // ov [q,e]
__device__ __align__(256) __half g_mm_h [NB * D_MODEL * D_MODEL];  // MmT [e,j]
__device__ __align__(256) __half g_pa_h [MTOT * D_MODEL];          // col-softmaxed A
__device__ __align__(256) float  g_f1  [MTOT * D_MODEL];           // fp32 staging (s1)
__device__ __align__(256) float  g_f2  [MTOT * D_MODEL];           // fp32 staging (S2)

// ---------------- helpers ----------------
__device__ __forceinline__ uint32_t smem_u32(const void* p) {
    uint32_t a;
    asm("{ .reg .u64 t; cvta.to.shared.u64 t, %1; cvt.u32.u64 %0, t; }" : "=r"(a) : "l"(p));
    return a;
}
__device__ __forceinline__ void cp16(uint32_t dst, const void* src) {
    asm volatile("cp.async.cg.shared.global [%0], [%1], 16;" :: "r"(dst), "l"(src) : "memory");
}
__device__ __forceinline__ void cp_commit() {
    asm volatile("cp.async.commit_group;" ::: "memory");
}

#define LDSM4(r, addr)                                                            \
    asm volatile("ldmatrix.sync.aligned.m8n8.x4.shared.b16 {%0,%1,%2,%3}, [%4];"  \
                 : "=r"((r)[0]), "=r"((r)[1]), "=r"((r)[2]), "=r"((r)[3])         \
                 : "r"(addr))

#define LDSM4T(r, addr)                                                                 \
    asm volatile("ldmatrix.sync.aligned.m8n8.x4.trans.shared.b16 {%0,%1,%2,%3}, [%4];"  \
                 : "=r"((r)[0]), "=r"((r)[1]), "=r"((r)[2]), "=r"((r)[3])               \
                 : "r"(addr))

#define MMA_F16(d, a, b)                                                           \
    asm volatile("mma.sync.aligned.m16n8k16.row.col.f32.f16.f16.f32 "              \
                 "{%0,%1,%2,%3}, {%4,%5,%6,%7}, {%8,%9}, {%0,%1,%2,%3};"           \
                 : "+f"((d)[0]), "+f"((d)[1]), "+f"((d)[2]), "+f"((d)[3])          \
                 : "r"((a)[0]), "r"((a)[1]), "r"((a)[2]), "r"((a)[3]),             \
                   "r"((b)[0]), "r"((b)[1]))

// ---------------- common GEMM config ----------------
// BM=128, BN=128, BK=64. 256 threads = 8 warps (2x4), warp tile 64x32.
// smem/stage: A 16K | B 16K = 32KB; 3 stages = 96KB; 2 CTAs/SM.
#define STG_BYTES 32768u
#define NSTAGE    3
#define SMEM_BYTES (NSTAGE * 32768)

// =======================================================================
// gemm_body: C tile = A[M,K] @ B[N,K]^T (+bias), both K-contiguous.
// Ah/Bh pre-offset to the (bm, bn) tile.
// =======================================================================
#define LOAD_STAGE(sidx) do {                                                        \
    const uint32_t base_ = sb + (uint32_t)((sidx) % 3) * STG_BYTES;                  \
    const int k0_ = (sidx) * 64;                                                     \
    _Pragma("unroll")                                                                \
    for (int t_ = 0; t_ < 4; t_++) {                                                 \
        int idx_ = tid + 256 * t_;                                                   \
        int r_ = idx_ >> 3, c_ = idx_ & 7;                                           \
        uint32_t sm_ = base_ + (uint32_t)r_ * 128u +                                 \
                       ((uint32_t)(c_ * 16) ^ ((uint32_t)(r_ & 7) * 16u));           \
        cp16(sm_, Ah + (size_t)r_ * K + k0_ + c_ * 8);                               \
    }                                                                                \
    _Pragma("unroll")                                                                \
    for (int t_ = 0; t_ < 4; t_++) {                                                 \
        int idx_ = tid + 256 * t_;                                                   \
        int r_ = idx_ >> 3, c_ = idx_ & 7;                                           \
        uint32_t sm_ = base_ + 16384u + (uint32_t)r_ * 128u +                        \
                       ((uint32_t)(c_ * 16) ^ ((uint32_t)(r_ & 7) * 16u));           \
        cp16(sm_, Bh + (size_t)r_ * K + k0_ + c_ * 8);                               \
    }                                                                                \
    cp_commit();                                                                     \
} while (0)

__device__ __forceinline__ void gemm_body(
    const __half* __restrict__ Ah, const __half* __restrict__ Bh,
    const float* __restrict__ bias,
    float* __restrict__ Cf, __half* __restrict__ Ch,
    int N, int K, int bm, int bn, long long cOff)
{
    extern __shared__ char smem[];
    const uint32_t sb = smem_u32(smem);
    const int tid = threadIdx.x, lane = tid & 31, wid = tid >> 5;
    const int wm = wid >> 2, wn = wid & 3;

    const int nst = K >> 6;

    LOAD_STAGE(0);
    LOAD_STAGE(1);

    const uint32_t swz = ((uint32_t)(lane & 7)) << 4;
    const uint32_t acsel = (uint32_t)(lane >> 4);
    uint32_t aoff[4];
#pragma unroll
    for (int i = 0; i < 4; i++)
        aoff[i] = (uint32_t)(wm * 64 + i * 16 + (lane & 15)) * 128u;
    const uint32_t bcsel = (uint32_t)((lane >> 3) & 1);
    const int brow = (lane & 7) + ((lane >> 4) << 3);
    uint32_t boff[2];
#pragma unroll
    for (int jj = 0; jj < 2; jj++)
        boff[jj] = 16384u + (uint32_t)(wn * 32 + jj * 16 + brow) * 128u;

    float acc[4][4][4];
#pragma unroll
    for (int i = 0; i < 4; i++)
#pragma unroll
        for (int j = 0; j < 4; j++)
#pragma unroll
            for (int r = 0; r < 4; r++) acc[i][j][r] = 0.f;

    for (int s = 0; s < nst; s++) {
        const int rem = nst - 1 - s;
        if (rem >= 1) asm volatile("cp.async.wait_group 1;" ::: "memory");
        else          asm volatile("cp.async.wait_group 0;" ::: "memory");
        __syncthreads();
        if (s + 2 < nst) LOAD_STAGE(s + 2);

        const uint32_t st = sb + (uint32_t)(s % 3) * STG_BYTES;
#pragma unroll
        for (int ks = 0; ks < 4; ks++) {
            uint32_t af[4][4];
            const uint32_t ak = (((uint32_t)(2 * ks) + acsel) << 4) ^ swz;
#pragma unroll
            for (int i = 0; i < 4; i++)
                LDSM4(af[i], st + aoff[i] + ak);
            const uint32_t bk = (((uint32_t)(2 * ks) + bcsel) << 4) ^ swz;
#pragma unroll
            for (int jj = 0; jj < 2; jj++) {
                uint32_t bf[4];
                LDSM4(bf, st + boff[jj] + bk);
#pragma unroll
                for (int i = 0; i < 4; i++) {
                    MMA_F16(acc[i][jj * 2 + 0], af[i], bf);
                    MMA_F16(acc[i][jj * 2 + 1], af[i], bf + 2);
                }
            }
        }
    }

    const int g = lane >> 2, tig = lane & 3;
#pragma unroll
    for (int i = 0; i < 4; i++) {
        const long long m0 = bm + wm * 64 + i * 16 + g;
#pragma unroll
        for (int j = 0; j < 4; j++) {
            const int n = bn + wn * 32 + j * 8 + tig * 2;
            const float b0 = bias ? bias[n] : 0.f;
            const float b1 = bias ? bias[n + 1] : 0.f;
#pragma unroll
            for (int h = 0; h < 2; h++) {
                const float v0 = acc[i][j][2 * h]     + b0;
                const float v1 = acc[i][j][2 * h + 1] + b1;
                const long long o = cOff + (m0 + 8 * h) * (long long)N + n;
                if (Cf) *(float2*)(Cf + o) = make_float2(v0, v1);
                else    *(__half2*)(Ch + o) = __floats2half2_rn(v0, v1);
            }
        }
    }
}

// generic single-GEMM wrapper (G2, G4, G7)
__global__ void __launch_bounds__(256, 2)
gemm_f16(const __half* __restrict__ Ah, const __half* __restrict__ Bh,
         const float* __restrict__ bias,
         float* __restrict__ Cf, __half* __restrict__ Ch,
         int N, int K,
         long long aB, long long bB, long long cB)
{
    const long long z = blockIdx.z;
    const int bm = blockIdx.y * 128, bn = blockIdx.x * 128;
    gemm_body(Ah + z * aB + (long long)bm * K,
              Bh + z * bB + (long long)bn * K,
              bias, Cf, Ch, N, K, bm, bn, z * cB);
}

// merged G1/G3/G5: grid.z in {0,1,2} selects the job.
__global__ void __launch_bounds__(256, 2)
gemm_f16_proj3(const __half* __restrict__ A0, const __half* __restrict__ A1,
               const __half* __restrict__ A2, const __half* __restrict__ W,
               const float* __restrict__ b0, const float* __restrict__ b1,
               const float* __restrict__ b2,
               __half* __restrict__ C0, __half* __restrict__ C1,
               __half* __restrict__ C2)
{
    const int zz = blockIdx.z;
    const int NW = D_MODEL * D_MODEL;
    const __half* A = (zz == 0) ? A0 : (zz == 1) ? A1 : A2;
    const __half* B = (zz == 0) ? W : (zz == 1) ? W + 2 * NW : W + 4 * NW;
    const float* bias = (zz == 0) ? b0 : (zz == 1) ? b1 : b2;
    __half* C = (zz == 0) ? C0 : (zz == 1) ? C1 : C2;
    const int bm = blockIdx.y * 128, bn = blockIdx.x * 128;
    gemm_body(A + (long long)bm * D_MODEL, B + (long long)bn * D_MODEL,
              bias, nullptr, C, D_MODEL, D_MODEL, bm, bn, 0);
}

// =======================================================================
// gemm_f16_tt: C[e,j] = sum_q A[q,e] * B[q,j]  (both stored [K=q, 1024])
// ldmatrix.trans both operands. BM=BN=128. A/B tiles [64q x 128], 256B rows.
// =======================================================================
#define LOAD_STAGE_TT(sidx) do {                                                     \
    const uint32_t base_ = sb + (uint32_t)((sidx) % 3) * STG_BYTES;                  \
    const int k0_ = (sidx) * 64;                                                     \
    _Pragma("unroll")                                                                \
    for (int t_ = 0; t_ < 4; t_++) {                                                 \
        int idx_ = tid + 256 * t_;                                                   \
        int r_ = idx_ >> 4, u_ = idx_ & 15;                                          \
        uint32_t sm_ = base_ + (uint32_t)r_ * 256u +                                 \
                       ((uint32_t)(u_ ^ (r_ & 7)) << 4);                             \
        cp16(sm_, Ag + (size_t)(k0_ + r_) * D_MODEL + bm + u_ * 8);                  \
    }                                                                                \
    _Pragma("unroll")                                                                \
    for (int t_ = 0; t_ < 4; t_++) {                                                 \
        int idx_ = tid + 256 * t_;                                                   \
        int r_ = idx_ >> 4, u_ = idx_ & 15;                                          \
        uint32_t sm_ = base_ + 16384u + (uint32_t)r_ * 256u +                        \
                       ((uint32_t)(u_ ^ (r_ & 7)) << 4);                             \
        cp16(sm_, Bg + (size_t)(k0_ + r_) * D_MODEL + bn + u_ * 8);                  \
    }                                                                                \
    cp_commit();                                                                     \
} while (0)

__global__ void __launch_bounds__(256, 2)
gemm_f16_tt(const __half* __restrict__ A, const __half* __restrict__ B,
            __half* __restrict__ C, int Kdim,
            long long aB, long long bB, long long cB)
{
    extern __shared__ char smem[];
    const uint32_t sb = smem_u32(smem);
    const int tid = threadIdx.x, lane = tid & 31, wid = tid >> 5;
    const int wm = wid >> 2, wn = wid & 3;
    const long long z = blockIdx.z;
    const int bm = blockIdx.y * 128, bn = blockIdx.x * 128;

    const __half* Ag = A + z * aB;
    const __half* Bg = B + z * bB;

    const int nst = Kdim >> 6;

    LOAD_STAGE_TT(0);
    LOAD_STAGE_TT(1);

    const uint32_t l7 = (uint32_t)(lane & 7);
    const int arow_k = ((lane >> 4) << 3) + (lane & 7);
    const uint32_t auadd = (uint32_t)((lane >> 3) & 1);
    const int brow_k = (((lane >> 3) & 1) << 3) + (lane & 7);
    const uint32_t buadd = (uint32_t)(lane >> 4);

    float acc[4][4][4];
#pragma unroll
    for (int i = 0; i < 4; i++)
#pragma unroll
        for (int j = 0; j < 4; j++)
#pragma unroll
            for (int r = 0; r < 4; r++) acc[i][j][r] = 0.f;

    for (int s = 0; s < nst; s++) {
        const int rem = nst - 1 - s;
        if (rem >= 1) asm volatile("cp.async.wait_group 1;" ::: "memory");
        else          asm volatile("cp.async.wait_group 0;" ::: "memory");
        __syncthreads();
        if (s + 2 < nst) LOAD_STAGE_TT(s + 2);

        const uint32_t st = sb + (uint32_t)(s % 3) * STG_BYTES;
#pragma unroll
        for (int ks = 0; ks < 4; ks++) {
            const uint32_t ra = (uint32_t)(ks * 16 + arow_k);
            const uint32_t rb = (uint32_t)(ks * 16 + brow_k);
            uint32_t af[4][4];
#pragma unroll
            for (int i = 0; i < 4; i++) {
                const uint32_t unit = (uint32_t)(wm * 8 + 2 * i) + auadd;
                LDSM4T(af[i], st + ra * 256u + ((unit ^ l7) << 4));
            }
#pragma unroll
            for (int jj = 0; jj < 2; jj++) {
                uint32_t bf[4];
                const uint32_t unit = (uint32_t)(wn * 4 + 2 * jj) + buadd;
                LDSM4T(bf, st + 16384u + rb * 256u + ((unit ^ l7) << 4));
#pragma unroll
                for (int i = 0; i < 4; i++) {
                    MMA_F16(acc[i][jj * 2 + 0], af[i], bf);
                    MMA_F16(acc[i][jj * 2 + 1], af[i], bf + 2);
                }
            }
        }
    }

    const int g = lane >> 2, tig = lane & 3;
#pragma unroll
    for (int i = 0; i < 4; i++) {
        const long long m0 = bm + wm * 64 + i * 16 + g;
#pragma unroll
        for (int j = 0; j < 4; j++) {
            const int n = bn + wn * 32 + j * 8 + tig * 2;
#pragma unroll
            for (int h = 0; h < 2; h++) {
                const long long o = (z * cB) + (m0 + 8 * h) * (long long)D_MODEL + n;
                *(__half2*)(C + o) = __floats2half2_rn(acc[i][j][2 * h],
                                                       acc[i][j][2 * h + 1]);
            }
        }
    }
}

// ---------------- aux kernels ----------------
__global__ __launch_bounds__(256)
void tohalf_kernel(const float4* __restrict__ in, __half2* __restrict__ out, int n4)
{
    int i = blockIdx.x * 256 + threadIdx.x;
    if (i < n4) {
        float4 v = in[i];
        out[2 * i]     = __floats2half2_rn(v.x, v.y);
        out[2 * i + 1] = __floats2half2_rn(v.z, v.w);
    }
}

__global__ __launch_bounds__(256)
void tohalf5_kernel(const float4* __restrict__ w0, const float4* __restrict__ w1,
                    const float4* __restrict__ w2, const float4* __restrict__ w3,
                    const float4* __restrict__ w4, __half2* __restrict__ out)
{
    const int seg = blockIdx.x >> 10;
    const int i = ((blockIdx.x & 1023) * 256 + threadIdx.x);
    const float4* src = (seg == 0) ? w0 : (seg == 1) ? w1 : (seg == 2) ? w2
                       : (seg == 3) ? w3 : w4;
    float4 v = src[i];
    __half2* o = out + (size_t)seg * (D_MODEL * D_MODEL / 2) + 2 * (size_t)i;
    o[0] = __floats2half2_rn(v.x, v.y);
    o[1] = __floats2half2_rn(v.z, v.w);
}

__global__ __launch_bounds__(256)
void softmax_rows_1024(const float* __restrict__ X, __half* __restrict__ O)
{
    const float* p = X + (long long)blockIdx.x * 1024;
    __half* q = O + (long long)blockIdx.x * 1024;
    const int t = threadIdx.x;
    __shared__ float red[256];
    float v[4];
#pragma unroll
    for (int j = 0; j < 4; j++) v[j] = p[t + 256 * j];
    float mx = fmaxf(fmaxf(v[0], v[1]), fmaxf(v[2], v[3]));
    red[t] = mx; __syncthreads();
    for (int s = 128; s > 0; s >>= 1) { if (t < s) red[t] = fmaxf(red[t], red[t + s]); __syncthreads(); }
    mx = red[0]; __syncthreads();
    float s = 0.f;
#pragma unroll
    for (int j = 0; j < 4; j++) { v[j] = __expf(v[j] - mx); s += v[j]; }
    red[t] = s; __syncthreads();
    for (int s2 = 128; s2 > 0; s2 >>= 1) { if (t < s2) red[t] += red[t + s2]; __syncthreads(); }
    const float inv = 1.f / red[0];
#pragma unroll
    for (int j = 0; j < 4; j++) q[t + 256 * j] = __float2half(v[j] * inv);
}

__global__ __launch_bounds__(256)
void softmax_cols_half(const float* __restrict__ X, __half* __restrict__ P)
{
    const int tx = threadIdx.x & 31;
    const int ty = threadIdx.x >> 5;
    const int c = blockIdx.x * 32 + tx;
    const long long zoff = (long long)blockIdx.y * T_SEQ * D_MODEL;
    const float* base = X + zoff + c;

    float mx = -1e30f, s = 0.f;
    for (int r = ty; r < T_SEQ; r += 8) {
        float x = base[(long long)r * D_MODEL];
        if (x > mx) { s = s * __expf(mx - x) + 1.f; mx = x; }
        else        { s += __expf(x - mx); }
    }
    __shared__ float smx[8][32], ssm[8][32];
    smx[ty][tx] = mx; ssm[ty][tx] = s;
    __syncthreads();
    if (ty == 0) {
        float M = smx[0][tx];
#pragma unroll
        for (int k = 1; k < 8; k++) M = fmaxf(M, smx[k][tx]);
        float S = 0.f;
#pragma unroll
        for (int k = 0; k < 8; k++) S += ssm[k][tx] * __expf(smx[k][tx] - M);
        smx[0][tx] = M; ssm[0][tx] = 1.f / S;
    }
    __syncthreads();
    const float M = smx[0][tx], inv = ssm[0][tx];
    for (int r = ty; r < T_SEQ; r += 8) {
        const long long o = zoff + (long long)r * D_MODEL + c;
        P[o] = __float2half(__expf(base[(long long)r * D_MODEL] - M) * inv);
    }
}

// ---------------- host launcher ----------------
extern "C" void kernel_launch(void* const* d_in, const int* in_sizes, int n_in,
                              void* d_out, int out_size)
{
    const float* latent = (const float*)d_in[0];
    const float* input  = (const float*)d_in[1];
    const float* Wl = (const float*)d_in[2];
    const float* bl = (const float*)d_in[3];
    const float* Wu = (const float*)d_in[4];
    const float* bu = (const float*)d_in[5];
    const float* WA = (const float*)d_in[6];
    const float* bA = (const float*)d_in[7];
    const float* WV = (const float*)d_in[8];
    const float* bV = (const float*)d_in[9];
    const float* Wo = (const float*)d_in[10];
    const float* bo = (const float*)d_in[11];
    float* out = (float*)d_out;

    __half *lat_h, *in_h, *w_h, *p1_h, *p2_h, *ls_h, *ov_h, *mm_h, *pa_h;
    float *f1, *f2;
    cudaGetSymbolAddress((void**)&lat_h, g_lat_h);
    cudaGetSymbolAddress((void**)&in_h,  g_in_h);
    cudaGetSymbolAddress((void**)&w_h,   g_w_h);
    cudaGetSymbolAddress((void**)&p1_h,  g_p1_h);
    cudaGetSymbolAddress((void**)&p2_h,  g_p2_h);
    cudaGetSymbolAddress((void**)&ls_h,  g_ls_h);
    cudaGetSymbolAddress((void**)&ov_h,  g_ov_h);
    cudaGetSymbolAddress((void**)&mm_h,  g_mm_h);
    cudaGetSymbolAddress((void**)&pa_h,  g_pa_h);
    cudaGetSymbolAddress((void**)&f1,    g_f1);
    cudaGetSymbolAddress((void**)&f2,    g_f2);

    cudaFuncSetAttribute(gemm_f16,
                         cudaFuncAttributeMaxDynamicSharedMemorySize, SMEM_BYTES);
    cudaFuncSetAttribute(gemm_f16_proj3,
                         cudaFuncAttributeMaxDynamicSharedMemorySize, SMEM_BYTES);
    cudaFuncSetAttribute(gemm_f16_tt,
                         cudaFuncAttributeMaxDynamicSharedMemorySize, SMEM_BYTES);

    const int D = D_MODEL;
    const int NW = D * D;
    const int NACT = MTOT * D;

    // 1-3: operand prep
    tohalf_kernel<<<NACT / 4 / 256, 256>>>((const float4*)latent, (__half2*)lat_h, NACT / 4);
    tohalf_kernel<<<NACT / 4 / 256, 256>>>((const float4*)input,  (__half2*)in_h,  NACT / 4);
    tohalf5_kernel<<<5 * (NW / 4 / 256), 256>>>((const float4*)Wl, (const float4*)Wu,
                                                (const float4*)WA, (const float4*)WV,
                                                (const float4*)Wo, (__half2*)w_h);

    dim3 thr(256);
    dim3 gProj(D / 128, MTOT / 128, 1);       // (8, 64)

    // 4: merged G1/G3/G5 -> p1, p2, ov (fp16), 1536 CTAs
    gemm_f16_proj3<<<dim3(D / 128, MTOT / 128, 3), thr, SMEM_BYTES>>>(
        lat_h, in_h, lat_h, w_h, bl, bA, bo, p1_h, p2_h, ov_h);

    // 5: G2: s1 = emb0 @ Wu^T + bu -> f1 (fp32)
    gemm_f16<<<gProj, thr, SMEM_BYTES>>>(p1_h, w_h + 1 * NW, bu,
                                         f1, nullptr, D, D, 0, 0, 0);
    // 6: G4: S2 = Dm @ WV^T + bV -> f2 (fp32)   [ncu profiles this launch]
    gemm_f16<<<gProj, thr, SMEM_BYTES>>>(p2_h, w_h + 3 * NW, bV,
                                         f2, nullptr, D, D, 0, 0, 0);
    // 7: row softmax -> L fp16 [q,j]
    softmax_rows_1024<<<MTOT, 256>>>(f1, ls_h);
    // 8: col softmax over T_kv -> pa fp16
    softmax_cols_half<<<dim3(D / 32, NB), 256>>>(f2, pa_h);

    // 9: G6 (trans-trans): MmT[e,j] = sum_q ov[q,e] * L[q,j]  -> mm fp16
    gemm_f16_tt<<<dim3(D / 128, D / 128, NB), thr, SMEM_BYTES>>>(
        ov_h, ls_h, mm_h, T_SEQ,
        (long long)T_SEQ * D, (long long)T_SEQ * D, (long long)D * D);

    // 10: G7: o[b] = pa @ MmT^T  (M=2048, N=1024, K=1024) -> d_out fp32
    gemm_f16<<<dim3(D / 128, T_SEQ / 128, NB), thr, SMEM_BYTES>>>(
        pa_h, mm_h, nullptr, out, nullptr,
        D, D, (long long)T_SEQ * D, (long long)D * D, (long long)T_SEQ * D);
}

// round 9
// speedup vs baseline: 1.1040x; 1.0528x over previous
#include <cuda_runtime.h>
#include <cuda_fp16.h>
#include <cstdint>
#include <math.h>

// ITAttention on GB300, sm_103 baseline ISA. mma.sync.m16n8k16 fp16 HMMA.
// Pipeline (associativity-restructured): o = A_sm @ (L^T @ ov)
// R9: 128-thread CTAs, 4 warps x (64x64) warp tiles, 2 CTAs/SM, reg cap 255.

#define D_MODEL 1024
#define T_SEQ   2048
#define NB      4
#define MTOT    (NB * T_SEQ)       // 8192

// ---------------- scratch (no allocation allowed) ----------------
__device__ __align__(256) __half g_lat_h[MTOT * D_MODEL];
__device__ __align__(256) __half g_in_h [MTOT * D_MODEL];
__device__ __align__(256) __half g_w_h  [5 * D_MODEL * D_MODEL];
__device__ __align__(256) __half g_p1_h [MTOT * D_MODEL];          // emb0
__device__ __align__(256) __half g_p2_h [MTOT * D_MODEL];          // Dm
__device__ __align__(256) __half g_ls_h [MTOT * D_MODEL];          // L (row-softmaxed) [q,j]
__device__ __align__(256) __half g_ov_h [MTOT * D_MODEL];          // ov [q,e]
__device__ __align__(256) __half g_mm_h [NB * D_MODEL * D_MODEL];  // MmT [e,j]
__device__ __align__(256) __half g_pa_h [MTOT * D_MODEL];          // col-softmaxed A
__device__ __align__(256) float  g_f1  [MTOT * D_MODEL];           // fp32 staging (s1)
__device__ __align__(256) float  g_f2  [MTOT * D_MODEL];           // fp32 staging (S2)

// ---------------- helpers ----------------
__device__ __forceinline__ uint32_t smem_u32(const void* p) {
    uint32_t a;
    asm("{ .reg .u64 t; cvta.to.shared.u64 t, %1; cvt.u32.u64 %0, t; }" : "=r"(a) : "l"(p));
    return a;
}
__device__ __forceinline__ void cp16(uint32_t dst, const void* src) {
    asm volatile("cp.async.cg.shared.global [%0], [%1], 16;" :: "r"(dst), "l"(src) : "memory");
}
__device__ __forceinline__ void cp_commit() {
    asm volatile("cp.async.commit_group;" ::: "memory");
}

#define LDSM4(r, addr)                                                            \
    asm volatile("ldmatrix.sync.aligned.m8n8.x4.shared.b16 {%0,%1,%2,%3}, [%4];"  \
                 : "=r"((r)[0]), "=r"((r)[1]), "=r"((r)[2]), "=r"((r)[3])         \
                 : "r"(addr))

#define LDSM4T(r, addr)                                                                 \
    asm volatile("ldmatrix.sync.aligned.m8n8.x4.trans.shared.b16 {%0,%1,%2,%3}, [%4];"  \
                 : "=r"((r)[0]), "=r"((r)[1]), "=r"((r)[2]), "=r"((r)[3])               \
                 : "r"(addr))

#define MMA_F16(d, a, b)                                                           \
    asm volatile("mma.sync.aligned.m16n8k16.row.col.f32.f16.f16.f32 "              \
                 "{%0,%1,%2,%3}, {%4,%5,%6,%7}, {%8,%9}, {%0,%1,%2,%3};"           \
                 : "+f"((d)[0]), "+f"((d)[1]), "+f"((d)[2]), "+f"((d)[3])          \
                 : "r"((a)[0]), "r"((a)[1]), "r"((a)[2]), "r"((a)[3]),             \
                   "r"((b)[0]), "r"((b)[1]))

// ---------------- common GEMM config ----------------
// BM=128, BN=128, BK=64. 128 threads = 4 warps (2x2), warp tile 64x64.
// smem/stage: A 16K | B 16K = 32KB; 3 stages = 96KB; 2 CTAs/SM (8 warps/SM).
#define STG_BYTES 32768u
#define NSTAGE    3
#define SMEM_BYTES (NSTAGE * 32768)
#define NTHR      128

// =======================================================================
// gemm_body: C tile = A[M,K] @ B[N,K]^T (+bias), both K-contiguous.
// Ah/Bh pre-offset to the (bm, bn) tile.
// =======================================================================
#define LOAD_STAGE(sidx) do {                                                        \
    const uint32_t base_ = sb + (uint32_t)((sidx) % 3) * STG_BYTES;                  \
    const int k0_ = (sidx) * 64;                                                     \
    _Pragma("unroll")                                                                \
    for (int t_ = 0; t_ < 8; t_++) {                                                 \
        int idx_ = tid + NTHR * t_;                                                  \
        int r_ = idx_ >> 3, c_ = idx_ & 7;                                           \
        uint32_t sm_ = base_ + (uint32_t)r_ * 128u +                                 \
                       ((uint32_t)(c_ * 16) ^ ((uint32_t)(r_ & 7) * 16u));           \
        cp16(sm_, Ah + (size_t)r_ * K + k0_ + c_ * 8);                               \
    }                                                                                \
    _Pragma("unroll")                                                                \
    for (int t_ = 0; t_ < 8; t_++) {                                                 \
        int idx_ = tid + NTHR * t_;                                                  \
        int r_ = idx_ >> 3, c_ = idx_ & 7;                                           \
        uint32_t sm_ = base_ + 16384u + (uint32_t)r_ * 128u +                        \
                       ((uint32_t)(c_ * 16) ^ ((uint32_t)(r_ & 7) * 16u));           \
        cp16(sm_, Bh + (size_t)r_ * K + k0_ + c_ * 8);                               \
    }                                                                                \
    cp_commit();                                                                     \
} while (0)

__device__ __forceinline__ void gemm_body(
    const __half* __restrict__ Ah, const __half* __restrict__ Bh,
    const float* __restrict__ bias,
    float* __restrict__ Cf, __half* __restrict__ Ch,
    int N, int K, int bm, int bn, long long cOff)
{
    extern __shared__ char smem[];
    const uint32_t sb = smem_u32(smem);
    const int tid = threadIdx.x, lane = tid & 31, wid = tid >> 5;
    const int wm = wid >> 1, wn = wid & 1;

    const int nst = K >> 6;

    LOAD_STAGE(0);
    LOAD_STAGE(1);

    const uint32_t swz = ((uint32_t)(lane & 7)) << 4;
    const uint32_t acsel = (uint32_t)(lane >> 4);
    uint32_t aoff[4];
#pragma unroll
    for (int i = 0; i < 4; i++)
        aoff[i] = (uint32_t)(wm * 64 + i * 16 + (lane & 15)) * 128u;
    const uint32_t bcsel = (uint32_t)((lane >> 3) & 1);
    const int brow = (lane & 7) + ((lane >> 4) << 3);
    uint32_t boff[4];
#pragma unroll
    for (int jj = 0; jj < 4; jj++)
        boff[jj] = 16384u + (uint32_t)(wn * 64 + jj * 16 + brow) * 128u;

    float acc[4][8][4];
#pragma unroll
    for (int i = 0; i < 4; i++)
#pragma unroll
        for (int j = 0; j < 8; j++)
#pragma unroll
            for (int r = 0; r < 4; r++) acc[i][j][r] = 0.f;

    for (int s = 0; s < nst; s++) {
        const int rem = nst - 1 - s;
        if (rem >= 1) asm volatile("cp.async.wait_group 1;" ::: "memory");
        else          asm volatile("cp.async.wait_group 0;" ::: "memory");
        __syncthreads();
        if (s + 2 < nst) LOAD_STAGE(s + 2);

        const uint32_t st = sb + (uint32_t)(s % 3) * STG_BYTES;
#pragma unroll
        for (int ks = 0; ks < 4; ks++) {
            uint32_t af[4][4];
            const uint32_t ak = (((uint32_t)(2 * ks) + acsel) << 4) ^ swz;
#pragma unroll
            for (int i = 0; i < 4; i++)
                LDSM4(af[i], st + aoff[i] + ak);
            const uint32_t bk = (((uint32_t)(2 * ks) + bcsel) << 4) ^ swz;
#pragma unroll
            for (int jj = 0; jj < 4; jj++) {
                uint32_t bf[4];
                LDSM4(bf, st + boff[jj] + bk);
#pragma unroll
                for (int i = 0; i < 4; i++) {
                    MMA_F16(acc[i][jj * 2 + 0], af[i], bf);
                    MMA_F16(acc[i][jj * 2 + 1], af[i], bf + 2);
                }
            }
        }
    }

    const int g = lane >> 2, tig = lane & 3;
#pragma unroll
    for (int i = 0; i < 4; i++) {
        const long long m0 = bm + wm * 64 + i * 16 + g;
#pragma unroll
        for (int j = 0; j < 8; j++) {
            const int n = bn + wn * 64 + j * 8 + tig * 2;
            const float b0 = bias ? bias[n] : 0.f;
            const float b1 = bias ? bias[n + 1] : 0.f;
#pragma unroll
            for (int h = 0; h < 2; h++) {
                const float v0 = acc[i][j][2 * h]     + b0;
                const float v1 = acc[i][j][2 * h + 1] + b1;
                const long long o = cOff + (m0 + 8 * h) * (long long)N + n;
                if (Cf) *(float2*)(Cf + o) = make_float2(v0, v1);
                else    *(__half2*)(Ch + o) = __floats2half2_rn(v0, v1);
            }
        }
    }
}

// generic single-GEMM wrapper (G7)
__global__ void __launch_bounds__(NTHR, 2)
gemm_f16(const __half* __restrict__ Ah, const __half* __restrict__ Bh,
         const float* __restrict__ bias,
         float* __restrict__ Cf, __half* __restrict__ Ch,
         int N, int K,
         long long aB, long long bB, long long cB)
{
    const long long z = blockIdx.z;
    const int bm = blockIdx.y * 128, bn = blockIdx.x * 128;
    gemm_body(Ah + z * aB + (long long)bm * K,
              Bh + z * bB + (long long)bn * K,
              bias, Cf, Ch, N, K, bm, bn, z * cB);
}

// merged G1/G3/G5: grid.z in {0,1,2} selects the job.
__global__ void __launch_bounds__(NTHR, 2)
gemm_f16_proj3(const __half* __restrict__ A0, const __half* __restrict__ A1,
               const __half* __restrict__ A2, const __half* __restrict__ W,
               const float* __restrict__ b0, const float* __restrict__ b1,
               const float* __restrict__ b2,
               __half* __restrict__ C0, __half* __restrict__ C1,
               __half* __restrict__ C2)
{
    const int zz = blockIdx.z;
    const int NW = D_MODEL * D_MODEL;
    const __half* A = (zz == 0) ? A0 : (zz == 1) ? A1 : A2;
    const __half* B = (zz == 0) ? W : (zz == 1) ? W + 2 * NW : W + 4 * NW;
    const float* bias = (zz == 0) ? b0 : (zz == 1) ? b1 : b2;
    __half* C = (zz == 0) ? C0 : (zz == 1) ? C1 : C2;
    const int bm = blockIdx.y * 128, bn = blockIdx.x * 128;
    gemm_body(A + (long long)bm * D_MODEL, B + (long long)bn * D_MODEL,
              bias, nullptr, C, D_MODEL, D_MODEL, bm, bn, 0);
}

// merged G2/G4: grid.z in {0,1}, fp32 outputs f1/f2.
__global__ void __launch_bounds__(NTHR, 2)
gemm_f16_pair(const __half* __restrict__ A0, const __half* __restrict__ A1,
              const __half* __restrict__ W,
              const float* __restrict__ b0, const float* __restrict__ b1,
              float* __restrict__ C0, float* __restrict__ C1)
{
    const int zz = blockIdx.z;
    const int NW = D_MODEL * D_MODEL;
    const __half* A = (zz == 0) ? A0 : A1;
    const __half* B = (zz == 0) ? W + 1 * NW : W + 3 * NW;
    const float* bias = (zz == 0) ? b0 : b1;
    float* C = (zz == 0) ? C0 : C1;
    const int bm = blockIdx.y * 128, bn = blockIdx.x * 128;
    gemm_body(A + (long long)bm * D_MODEL, B + (long long)bn * D_MODEL,
              bias, C, nullptr, D_MODEL, D_MODEL, bm, bn, 0);
}

// =======================================================================
// gemm_f16_tt: C[e,j] = sum_q A[q,e] * B[q,j]  (both stored [K=q, 1024])
// ldmatrix.trans both operands. BM=BN=128, tiles [64q x 128], 256B rows.
// =======================================================================
#define LOAD_STAGE_TT(sidx) do {                                                     \
    const uint32_t base_ = sb + (uint32_t)((sidx) % 3) * STG_BYTES;                  \
    const int k0_ = (sidx) * 64;                                                     \
    _Pragma("unroll")                                                                \
    for (int t_ = 0; t_ < 8; t_++) {                                                 \
        int idx_ = tid + NTHR * t_;                                                  \
        int r_ = idx_ >> 4, u_ = idx_ & 15;                                          \
        uint32_t sm_ = base_ + (uint32_t)r_ * 256u +                                 \
                       ((uint32_t)(u_ ^ (r_ & 7)) << 4);                             \
        cp16(sm_, Ag + (size_t)(k0_ + r_) * D_MODEL + bm + u_ * 8);                  \
    }                                                                                \
    _Pragma("unroll")                                                                \
    for (int t_ = 0; t_ < 8; t_++) {                                                 \
        int idx_ = tid + NTHR * t_;                                                  \
        int r_ = idx_ >> 4, u_ = idx_ & 15;                                          \
        uint32_t sm_ = base_ + 16384u + (uint32_t)r_ * 256u +                        \
                       ((uint32_t)(u_ ^ (r_ & 7)) << 4);                             \
        cp16(sm_, Bg + (size_t)(k0_ + r_) * D_MODEL + bn + u_ * 8);                  \
    }                                                                                \
    cp_commit();                                                                     \
} while (0)

__global__ void __launch_bounds__(NTHR, 2)
gemm_f16_tt(const __half* __restrict__ A, const __half* __restrict__ B,
            __half* __restrict__ C, int Kdim,
            long long aB, long long bB, long long cB)
{
    extern __shared__ char smem[];
    const uint32_t sb = smem_u32(smem);
    const int tid = threadIdx.x, lane = tid & 31, wid = tid >> 5;
    const int wm = wid >> 1, wn = wid & 1;
    const long long z = blockIdx.z;
    const int bm = blockIdx.y * 128, bn = blockIdx.x * 128;

    const __half* Ag = A + z * aB;
    const __half* Bg = B + z * bB;

    const int nst = Kdim >> 6;

    LOAD_STAGE_TT(0);
    LOAD_STAGE_TT(1);

    const uint32_t l7 = (uint32_t)(lane & 7);
    const int arow_k = ((lane >> 4) << 3) + (lane & 7);
    const uint32_t auadd = (uint32_t)((lane >> 3) & 1);
    const int brow_k = (((lane >> 3) & 1) << 3) + (lane & 7);
    const uint32_t buadd = (uint32_t)(lane >> 4);

    float acc[4][8][4];
#pragma unroll
    for (int i = 0; i < 4; i++)
#pragma unroll
        for (int j = 0; j < 8; j++)
#pragma unroll
            for (int r = 0; r < 4; r++) acc[i][j][r] = 0.f;

    for (int s = 0; s < nst; s++) {
        const int rem = nst - 1 - s;
        if (rem >= 1) asm volatile("cp.async.wait_group 1;" ::: "memory");
        else          asm volatile("cp.async.wait_group 0;" ::: "memory");
        __syncthreads();
        if (s + 2 < nst) LOAD_STAGE_TT(s + 2);

        const uint32_t st = sb + (uint32_t)(s % 3) * STG_BYTES;
#pragma unroll
        for (int ks = 0; ks < 4; ks++) {
            const uint32_t ra = (uint32_t)(ks * 16 + arow_k);
            const uint32_t rb = (uint32_t)(ks * 16 + brow_k);
            uint32_t af[4][4];
#pragma unroll
            for (int i = 0; i < 4; i++) {
                const uint32_t unit = (uint32_t)(wm * 8 + 2 * i) + auadd;
                LDSM4T(af[i], st + ra * 256u + ((unit ^ l7) << 4));
            }
#pragma unroll
            for (int jj = 0; jj < 4; jj++) {
                uint32_t bf[4];
                const uint32_t unit = (uint32_t)(wn * 8 + 2 * jj) + buadd;
                LDSM4T(bf, st + 16384u + rb * 256u + ((unit ^ l7) << 4));
#pragma unroll
                for (int i = 0; i < 4; i++) {
                    MMA_F16(acc[i][jj * 2 + 0], af[i], bf);
                    MMA_F16(acc[i][jj * 2 + 1], af[i], bf + 2);
                }
            }
        }
    }

    const int g = lane >> 2, tig = lane & 3;
#pragma unroll
    for (int i = 0; i < 4; i++) {
        const long long m0 = bm + wm * 64 + i * 16 + g;
#pragma unroll
        for (int j = 0; j < 8; j++) {
            const int n = bn + wn * 64 + j * 8 + tig * 2;
#pragma unroll
            for (int h = 0; h < 2; h++) {
                const long long o = (z * cB) + (m0 + 8 * h) * (long long)D_MODEL + n;
                *(__half2*)(C + o) = __floats2half2_rn(acc[i][j][2 * h],
                                                       acc[i][j][2 * h + 1]);
            }
        }
    }
}

// ---------------- aux kernels ----------------
__global__ __launch_bounds__(256)
void tohalf_kernel(const float4* __restrict__ in, __half2* __restrict__ out, int n4)
{
    int i = blockIdx.x * 256 + threadIdx.x;
    if (i < n4) {
        float4 v = in[i];
        out[2 * i]     = __floats2half2_rn(v.x, v.y);
        out[2 * i + 1] = __floats2half2_rn(v.z, v.w);
    }
}

__global__ __launch_bounds__(256)
void tohalf5_kernel(const float4* __restrict__ w0, const float4* __restrict__ w1,
                    const float4* __restrict__ w2, const float4* __restrict__ w3,
                    const float4* __restrict__ w4, __half2* __restrict__ out)
{
    const int seg = blockIdx.x >> 10;
    const int i = ((blockIdx.x & 1023) * 256 + threadIdx.x);
    const float4* src = (seg == 0) ? w0 : (seg == 1) ? w1 : (seg == 2) ? w2
                       : (seg == 3) ? w3 : w4;
    float4 v = src[i];
    __half2* o = out + (size_t)seg * (D_MODEL * D_MODEL / 2) + 2 * (size_t)i;
    o[0] = __floats2half2_rn(v.x, v.y);
    o[1] = __floats2half2_rn(v.z, v.w);
}

__global__ __launch_bounds__(256)
void softmax_rows_1024(const float* __restrict__ X, __half* __restrict__ O)
{
    const float* p = X + (long long)blockIdx.x * 1024;
    __half* q = O + (long long)blockIdx.x * 1024;
    const int t = threadIdx.x;
    __shared__ float red[256];
    float v[4];
#pragma unroll
    for (int j = 0; j < 4; j++) v[j] = p[t + 256 * j];
    float mx = fmaxf(fmaxf(v[0], v[1]), fmaxf(v[2], v[3]));
    red[t] = mx; __syncthreads();
    for (int s = 128; s > 0; s >>= 1) { if (t < s) red[t] = fmaxf(red[t], red[t + s]); __syncthreads(); }
    mx = red[0]; __syncthreads();
    float s = 0.f;
#pragma unroll
    for (int j = 0; j < 4; j++) { v[j] = __expf(v[j] - mx); s += v[j]; }
    red[t] = s; __syncthreads();
    for (int s2 = 128; s2 > 0; s2 >>= 1) { if (t < s2) red[t] += red[t + s2]; __syncthreads(); }
    const float inv = 1.f / red[0];
#pragma unroll
    for (int j = 0; j < 4; j++) q[t + 256 * j] = __float2half(v[j] * inv);
}

__global__ __launch_bounds__(256)
void softmax_cols_half(const float* __restrict__ X, __half* __restrict__ P)
{
    const int tx = threadIdx.x & 31;
    const int ty = threadIdx.x >> 5;
    const int c = blockIdx.x * 32 + tx;
    const long long zoff = (long long)blockIdx.y * T_SEQ * D_MODEL;
    const float* base = X + zoff + c;

    float mx = -1e30f, s = 0.f;
    for (int r = ty; r < T_SEQ; r += 8) {
        float x = base[(long long)r * D_MODEL];
        if (x > mx) { s = s * __expf(mx - x) + 1.f; mx = x; }
        else        { s += __expf(x - mx); }
    }
    __shared__ float smx[8][32], ssm[8][32];
    smx[ty][tx] = mx; ssm[ty][tx] = s;
    __syncthreads();
    if (ty == 0) {
        float M = smx[0][tx];
#pragma unroll
        for (int k = 1; k < 8; k++) M = fmaxf(M, smx[k][tx]);
        float S = 0.f;
#pragma unroll
        for (int k = 0; k < 8; k++) S += ssm[k][tx] * __expf(smx[k][tx] - M);
        smx[0][tx] = M; ssm[0][tx] = 1.f / S;
    }
    __syncthreads();
    const float M = smx[0][tx], inv = ssm[0][tx];
    for (int r = ty; r < T_SEQ; r += 8) {
        const long long o = zoff + (long long)r * D_MODEL + c;
        P[o] = __float2half(__expf(base[(long long)r * D_MODEL] - M) * inv);
    }
}

// ---------------- host launcher ----------------
extern "C" void kernel_launch(void* const* d_in, const int* in_sizes, int n_in,
                              void* d_out, int out_size)
{
    const float* latent = (const float*)d_in[0];
    const float* input  = (const float*)d_in[1];
    const float* Wl = (const float*)d_in[2];
    const float* bl = (const float*)d_in[3];
    const float* Wu = (const float*)d_in[4];
    const float* bu = (const float*)d_in[5];
    const float* WA = (const float*)d_in[6];
    const float* bA = (const float*)d_in[7];
    const float* WV = (const float*)d_in[8];
    const float* bV = (const float*)d_in[9];
    const float* Wo = (const float*)d_in[10];
    const float* bo = (const float*)d_in[11];
    float* out = (float*)d_out;

    __half *lat_h, *in_h, *w_h, *p1_h, *p2_h, *ls_h, *ov_h, *mm_h, *pa_h;
    float *f1, *f2;
    cudaGetSymbolAddress((void**)&lat_h, g_lat_h);
    cudaGetSymbolAddress((void**)&in_h,  g_in_h);
    cudaGetSymbolAddress((void**)&w_h,   g_w_h);
    cudaGetSymbolAddress((void**)&p1_h,  g_p1_h);
    cudaGetSymbolAddress((void**)&p2_h,  g_p2_h);
    cudaGetSymbolAddress((void**)&ls_h,  g_ls_h);
    cudaGetSymbolAddress((void**)&ov_h,  g_ov_h);
    cudaGetSymbolAddress((void**)&mm_h,  g_mm_h);
    cudaGetSymbolAddress((void**)&pa_h,  g_pa_h);
    cudaGetSymbolAddress((void**)&f1,    g_f1);
    cudaGetSymbolAddress((void**)&f2,    g_f2);

    cudaFuncSetAttribute(gemm_f16,
                         cudaFuncAttributeMaxDynamicSharedMemorySize, SMEM_BYTES);
    cudaFuncSetAttribute(gemm_f16_proj3,
                         cudaFuncAttributeMaxDynamicSharedMemorySize, SMEM_BYTES);
    cudaFuncSetAttribute(gemm_f16_pair,
                         cudaFuncAttributeMaxDynamicSharedMemorySize, SMEM_BYTES);
    cudaFuncSetAttribute(gemm_f16_tt,
                         cudaFuncAttributeMaxDynamicSharedMemorySize, SMEM_BYTES);

    const int D = D_MODEL;
    const int NW = D * D;
    const int NACT = MTOT * D;

    // 1-3: operand prep
    tohalf_kernel<<<NACT / 4 / 256, 256>>>((const float4*)latent, (__half2*)lat_h, NACT / 4);
    tohalf_kernel<<<NACT / 4 / 256, 256>>>((const float4*)input,  (__half2*)in_h,  NACT / 4);
    tohalf5_kernel<<<5 * (NW / 4 / 256), 256>>>((const float4*)Wl, (const float4*)Wu,
                                                (const float4*)WA, (const float4*)WV,
                                                (const float4*)Wo, (__half2*)w_h);

    dim3 thr(NTHR);

    // 4: merged G1/G3/G5 -> p1, p2, ov (fp16), 1536 CTAs
    gemm_f16_proj3<<<dim3(D / 128, MTOT / 128, 3), thr, SMEM_BYTES>>>(
        lat_h, in_h, lat_h, w_h, bl, bA, bo, p1_h, p2_h, ov_h);

    // 5: merged G2/G4 -> f1, f2 (fp32), 1024 CTAs
    gemm_f16_pair<<<dim3(D / 128, MTOT / 128, 2), thr, SMEM_BYTES>>>(
        p1_h, p2_h, w_h, bu, bV, f1, f2);

    // 6: row softmax -> L fp16 [q,j]
    softmax_rows_1024<<<MTOT, 256>>>(f1, ls_h);
    // 7: col softmax over T_kv -> pa fp16
    softmax_cols_half<<<dim3(D / 32, NB), 256>>>(f2, pa_h);

    // 8: G6 (trans-trans): MmT[e,j] = sum_q ov[q,e] * L[q,j]  -> mm fp16
    gemm_f16_tt<<<dim3(D / 128, D / 128, NB), thr, SMEM_BYTES>>>(
        ov_h, ls_h, mm_h, T_SEQ,
        (long long)T_SEQ * D, (long long)T_SEQ * D, (long long)D * D);

    // 9: G7: o[b] = pa @ MmT^T  (M=2048, N=1024, K=1024) -> d_out fp32
    gemm_f16<<<dim3(D / 128, T_SEQ / 128, NB), thr, SMEM_BYTES>>>(
        pa_h, mm_h, nullptr, out, nullptr,
        D, D, (long long)T_SEQ * D, (long long)D * D, (long long)T_SEQ * D);
}